// round 5
// baseline (speedup 1.0000x reference)
#include <cuda_runtime.h>
#include <cuda_bf16.h>

// SoftIndex: per-row out[s] = cumsum_s( tanh(x[s] - x[s-1]) ), first diff = 0.
// x: [8192, 8192] fp32, out: same shape.
// R5: persistent warps, dynamic row queue, depth-2 prefetch that streams
// SEAMLESSLY across row boundaries (last 2 prefetches of a row target the
// next row's first chunks), and a self-resetting work counter (no reset
// kernel). No smem, no __syncthreads.

#define S 8192
#define LPT 8                 // elements per lane per chunk
#define CHUNK 256             // 32 * LPT
#define NCHUNK 32             // S / CHUNK
#define THREADS 256
#define GRID 740              // 5 CTAs/SM on 148 SMs
#define NWARPS (GRID * (THREADS / 32))

__device__ unsigned int g_row_ctr = 0u;
__device__ unsigned int g_done    = 0u;

// tanh(d) = 1 - 2/(ex2(d * 2/ln2) + 1); exact saturation at +/-inf.
__device__ __forceinline__ float fast_tanh(float d)
{
    float e;
    asm("ex2.approx.f32 %0, %1;" : "=f"(e) : "f"(d * 2.885390081777927f));
    float r;
    asm("rcp.approx.f32 %0, %1;" : "=f"(r) : "f"(e + 1.0f));
    return fmaf(-2.0f, r, 1.0f);
}

__device__ __forceinline__ unsigned fetch_row(unsigned lane)
{
    unsigned r;
    if (lane == 0u) r = atomicAdd(&g_row_ctr, 1u);
    return __shfl_sync(0xffffffffu, r, 0);
}

__global__ __launch_bounds__(THREADS, 5)
void softindex_kernel(const float* __restrict__ x, float* __restrict__ out)
{
    const unsigned lane  = threadIdx.x & 31u;
    const int      lbase = (int)lane * LPT;

    unsigned row = fetch_row(lane);

    if (row < (unsigned)S) {
        const float* __restrict__ xr   = x   + (size_t)row * S;
        float* __restrict__       orow = out + (size_t)row * S;

        // Prime pipeline with chunks 0,1 of first row.
        float4 a0 = __ldcs(reinterpret_cast<const float4*>(xr + lbase));
        float4 b0 = __ldcs(reinterpret_cast<const float4*>(xr + lbase + 4));
        float4 a1 = __ldcs(reinterpret_cast<const float4*>(xr + CHUNK + lbase));
        float4 b1 = __ldcs(reinterpret_cast<const float4*>(xr + CHUNK + lbase + 4));

        // Fetch next row id now; latency hidden behind this row's 32 chunks.
        unsigned next_row = fetch_row(lane);

        for (;;) {
            const bool next_valid = next_row < (unsigned)S;
            const float* __restrict__ nxr =
                x + (size_t)(next_valid ? next_row : 0u) * S;

            float carry      = 0.0f;
            float chunk_last = 0.0f;

#pragma unroll 1
            for (int ch = 0; ch < NCHUNK; ch++) {
                // Prefetch chunk ch+2; wraps into next row's chunks 0/1.
                float4 na = make_float4(0.f, 0.f, 0.f, 0.f);
                float4 nb = na;
                const int pc = ch + 2;
                if (pc < NCHUNK) {
                    const float* pn = xr + pc * CHUNK + lbase;
                    na = __ldcs(reinterpret_cast<const float4*>(pn));
                    nb = __ldcs(reinterpret_cast<const float4*>(pn + 4));
                } else if (next_valid) {
                    const float* pn = nxr + (pc - NCHUNK) * CHUNK + lbase;
                    na = __ldcs(reinterpret_cast<const float4*>(pn));
                    nb = __ldcs(reinterpret_cast<const float4*>(pn + 4));
                }

                float v[LPT] = {a0.x, a0.y, a0.z, a0.w, b0.x, b0.y, b0.z, b0.w};

                // Neighbor for this lane's first diff.
                float prev = __shfl_up_sync(0xffffffffu, v[LPT - 1], 1);
                if (lane == 0u) prev = (ch == 0) ? v[0] : chunk_last;

                // Lane-local inclusive scan of tanh(diffs).
                float s[LPT];
                float run = 0.0f, p = prev;
#pragma unroll
                for (int i = 0; i < LPT; i++) {
                    run += fast_tanh(v[i] - p);
                    p = v[i];
                    s[i] = run;
                }
                const float tot = run;

                // Warp inclusive scan of lane totals.
                float ws = tot;
#pragma unroll
                for (int off = 1; off < 32; off <<= 1) {
                    float n = __shfl_up_sync(0xffffffffu, ws, off);
                    if (lane >= (unsigned)off) ws += n;
                }

                const float prefix = carry + (ws - tot);   // exclusive

                float* po = orow + ch * CHUNK + lbase;
                __stcs(reinterpret_cast<float4*>(po),
                       make_float4(prefix + s[0], prefix + s[1],
                                   prefix + s[2], prefix + s[3]));
                __stcs(reinterpret_cast<float4*>(po + 4),
                       make_float4(prefix + s[4], prefix + s[5],
                                   prefix + s[6], prefix + s[7]));

                carry      += __shfl_sync(0xffffffffu, ws, 31);
                chunk_last  = __shfl_sync(0xffffffffu, v[LPT - 1], 31);

                // Rotate pipeline.
                a0 = a1; b0 = b1;
                a1 = na; b1 = nb;
            }

            if (!next_valid) break;
            row  = next_row;
            xr   = nxr;
            orow = out + (size_t)row * S;
            next_row = fetch_row(lane);  // overlapped with next row's chunks
        }
    }

    // Last warp to finish resets the counters for the next launch
    // (graph replays the same kernel; counters must return to 0).
    if (lane == 0u) {
        __threadfence();
        unsigned d = atomicAdd(&g_done, 1u);
        if (d == (unsigned)(NWARPS - 1)) {
            g_row_ctr = 0u;
            g_done    = 0u;
        }
    }
}

extern "C" void kernel_launch(void* const* d_in, const int* in_sizes, int n_in,
                              void* d_out, int out_size)
{
    const float* x = (const float*)d_in[0];
    float* out     = (float*)d_out;
    (void)in_sizes; (void)n_in; (void)out_size;

    softindex_kernel<<<GRID, THREADS>>>(x, out);
}

// round 6
// speedup vs baseline: 1.0561x; 1.0561x over previous
#include <cuda_runtime.h>
#include <cuda_bf16.h>

// SoftIndex: per-row out[s] = cumsum_s( tanh(x[s] - x[s-1]) ), first diff = 0.
// x: [8192, 8192] fp32, out: same shape.
// R6: perfect static balance. 4096 warps (512 CTAs x 8 warps), each warp owns
// exactly TWO CONTIGUOUS rows (one 64 KB span) processed as 64 chunks of a
// single depth-2 register-prefetch pipeline. Carry resets at the row boundary
// (chunk 32). No atomics, no smem, no __syncthreads, single launch.

#define S 8192
#define LPT 8                 // elements per lane per chunk
#define CHUNK 256             // 32 * LPT
#define NCHUNK 32             // chunks per row
#define TOTCHUNK 64           // chunks per 2-row span
#define THREADS 256
#define GRID 512              // 4096 warps * 2 rows = 8192 rows

// tanh(d) = 1 - 2/(ex2(d * 2/ln2) + 1); exact saturation at +/-inf.
__device__ __forceinline__ float fast_tanh(float d)
{
    float e;
    asm("ex2.approx.f32 %0, %1;" : "=f"(e) : "f"(d * 2.885390081777927f));
    float r;
    asm("rcp.approx.f32 %0, %1;" : "=f"(r) : "f"(e + 1.0f));
    return fmaf(-2.0f, r, 1.0f);
}

__global__ __launch_bounds__(THREADS, 4)
void softindex_kernel(const float* __restrict__ x, float* __restrict__ out)
{
    const unsigned lane  = threadIdx.x & 31u;
    const int      gwarp = blockIdx.x * (THREADS / 32) + (threadIdx.x >> 5);
    const int      lbase = (int)lane * LPT;

    // Each warp owns rows 2*gwarp and 2*gwarp+1: one contiguous 16384-float span.
    const float* __restrict__ xr   = x   + (size_t)gwarp * 2 * S;
    float* __restrict__       orow = out + (size_t)gwarp * 2 * S;

    // Prime pipeline with chunks 0,1.
    float4 a0 = __ldcs(reinterpret_cast<const float4*>(xr + lbase));
    float4 b0 = __ldcs(reinterpret_cast<const float4*>(xr + lbase + 4));
    float4 a1 = __ldcs(reinterpret_cast<const float4*>(xr + CHUNK + lbase));
    float4 b1 = __ldcs(reinterpret_cast<const float4*>(xr + CHUNK + lbase + 4));

    float carry      = 0.0f;
    float chunk_last = 0.0f;

#pragma unroll 1
    for (int ch = 0; ch < TOTCHUNK; ch++) {
        // Prefetch chunk ch+2 of the 2-row span (uniform predicate).
        float4 na = make_float4(0.f, 0.f, 0.f, 0.f);
        float4 nb = na;
        if (ch + 2 < TOTCHUNK) {
            const float* pn = xr + (ch + 2) * CHUNK + lbase;
            na = __ldcs(reinterpret_cast<const float4*>(pn));
            nb = __ldcs(reinterpret_cast<const float4*>(pn + 4));
        }

        float v[LPT] = {a0.x, a0.y, a0.z, a0.w, b0.x, b0.y, b0.z, b0.w};

        // Row boundary: at ch==0 and ch==NCHUNK the cumsum restarts.
        const bool row_start = (ch == 0) | (ch == NCHUNK);
        if (row_start) carry = 0.0f;

        // Neighbor for this lane's first diff: previous lane's last element;
        // lane 0 uses previous chunk's last element, or v[0] at a row start
        // (diff -> 0, matching the reference's zeroed first element).
        float prev = __shfl_up_sync(0xffffffffu, v[LPT - 1], 1);
        if (lane == 0u) prev = row_start ? v[0] : chunk_last;

        // Lane-local inclusive scan of tanh(diffs).
        float s[LPT];
        float run = 0.0f, p = prev;
#pragma unroll
        for (int i = 0; i < LPT; i++) {
            run += fast_tanh(v[i] - p);
            p = v[i];
            s[i] = run;
        }
        const float tot = run;

        // Warp inclusive scan of lane totals.
        float ws = tot;
#pragma unroll
        for (int off = 1; off < 32; off <<= 1) {
            float n = __shfl_up_sync(0xffffffffu, ws, off);
            if (lane >= (unsigned)off) ws += n;
        }

        const float prefix = carry + (ws - tot);   // exclusive for this lane

        float* po = orow + ch * CHUNK + lbase;
        __stcs(reinterpret_cast<float4*>(po),
               make_float4(prefix + s[0], prefix + s[1],
                           prefix + s[2], prefix + s[3]));
        __stcs(reinterpret_cast<float4*>(po + 4),
               make_float4(prefix + s[4], prefix + s[5],
                           prefix + s[6], prefix + s[7]));

        carry      += __shfl_sync(0xffffffffu, ws, 31);
        chunk_last  = __shfl_sync(0xffffffffu, v[LPT - 1], 31);

        // Rotate pipeline.
        a0 = a1; b0 = b1;
        a1 = na; b1 = nb;
    }
}

extern "C" void kernel_launch(void* const* d_in, const int* in_sizes, int n_in,
                              void* d_out, int out_size)
{
    const float* x = (const float*)d_in[0];
    float* out     = (float*)d_out;
    (void)in_sizes; (void)n_in; (void)out_size;

    softindex_kernel<<<GRID, THREADS>>>(x, out);
}

// round 7
// speedup vs baseline: 1.1224x; 1.0628x over previous
#include <cuda_runtime.h>
#include <cuda_bf16.h>

// SoftIndex: per-row out[s] = cumsum_s( tanh(x[s] - x[s-1]) ), first diff = 0.
// x: [8192, 8192] fp32, out: same shape.
// R7: one row per warp, small CTAs (128 thr = 4 warps), GRID=2048 with CTA
// churn for fine-grained SM load balance, high occupancy (10 CTAs/SM target,
// 40 warps/SM) for latency hiding. Depth-2 register prefetch inside the row.
// No atomics, no smem, no __syncthreads.

#define S 8192
#define LPT 8                 // elements per lane per chunk
#define CHUNK 256             // 32 * LPT
#define NCHUNK 32             // chunks per row
#define THREADS 128
#define WARPS_PER_CTA 4
#define GRID (S / WARPS_PER_CTA)   // 2048 CTAs, one row per warp

// tanh(d) = 1 - 2/(ex2(d * 2/ln2) + 1); exact saturation at +/-inf.
__device__ __forceinline__ float fast_tanh(float d)
{
    float e;
    asm("ex2.approx.f32 %0, %1;" : "=f"(e) : "f"(d * 2.885390081777927f));
    float r;
    asm("rcp.approx.f32 %0, %1;" : "=f"(r) : "f"(e + 1.0f));
    return fmaf(-2.0f, r, 1.0f);
}

__global__ __launch_bounds__(THREADS, 10)
void softindex_kernel(const float* __restrict__ x, float* __restrict__ out)
{
    const unsigned lane  = threadIdx.x & 31u;
    const int      row   = blockIdx.x * WARPS_PER_CTA + (threadIdx.x >> 5);
    const int      lbase = (int)lane * LPT;

    const float* __restrict__ xr   = x   + (size_t)row * S;
    float* __restrict__       orow = out + (size_t)row * S;

    // Prime pipeline with chunks 0,1.
    float4 a0 = __ldcs(reinterpret_cast<const float4*>(xr + lbase));
    float4 b0 = __ldcs(reinterpret_cast<const float4*>(xr + lbase + 4));
    float4 a1 = __ldcs(reinterpret_cast<const float4*>(xr + CHUNK + lbase));
    float4 b1 = __ldcs(reinterpret_cast<const float4*>(xr + CHUNK + lbase + 4));

    float carry      = 0.0f;
    float chunk_last = 0.0f;

#pragma unroll 1
    for (int ch = 0; ch < NCHUNK; ch++) {
        // Prefetch chunk ch+2.
        float4 na = make_float4(0.f, 0.f, 0.f, 0.f);
        float4 nb = na;
        if (ch + 2 < NCHUNK) {
            const float* pn = xr + (ch + 2) * CHUNK + lbase;
            na = __ldcs(reinterpret_cast<const float4*>(pn));
            nb = __ldcs(reinterpret_cast<const float4*>(pn + 4));
        }

        float v[LPT] = {a0.x, a0.y, a0.z, a0.w, b0.x, b0.y, b0.z, b0.w};

        // Neighbor for this lane's first diff: previous lane's last element;
        // lane 0 uses previous chunk's last element, or v[0] at row start
        // (diff -> 0, matching the reference's zeroed first element).
        float prev = __shfl_up_sync(0xffffffffu, v[LPT - 1], 1);
        if (lane == 0u) prev = (ch == 0) ? v[0] : chunk_last;

        // Lane-local inclusive scan of tanh(diffs).
        float s[LPT];
        float run = 0.0f, p = prev;
#pragma unroll
        for (int i = 0; i < LPT; i++) {
            run += fast_tanh(v[i] - p);
            p = v[i];
            s[i] = run;
        }
        const float tot = run;

        // Warp inclusive scan of lane totals.
        float ws = tot;
#pragma unroll
        for (int off = 1; off < 32; off <<= 1) {
            float n = __shfl_up_sync(0xffffffffu, ws, off);
            if (lane >= (unsigned)off) ws += n;
        }

        const float prefix = carry + (ws - tot);   // exclusive for this lane

        float* po = orow + ch * CHUNK + lbase;
        __stcs(reinterpret_cast<float4*>(po),
               make_float4(prefix + s[0], prefix + s[1],
                           prefix + s[2], prefix + s[3]));
        __stcs(reinterpret_cast<float4*>(po + 4),
               make_float4(prefix + s[4], prefix + s[5],
                           prefix + s[6], prefix + s[7]));

        carry      += __shfl_sync(0xffffffffu, ws, 31);
        chunk_last  = __shfl_sync(0xffffffffu, v[LPT - 1], 31);

        // Rotate pipeline.
        a0 = a1; b0 = b1;
        a1 = na; b1 = nb;
    }
}

extern "C" void kernel_launch(void* const* d_in, const int* in_sizes, int n_in,
                              void* d_out, int out_size)
{
    const float* x = (const float*)d_in[0];
    float* out     = (float*)d_out;
    (void)in_sizes; (void)n_in; (void)out_size;

    softindex_kernel<<<GRID, THREADS>>>(x, out);
}